// round 11
// baseline (speedup 1.0000x reference)
#include <cuda_runtime.h>
#include <math.h>
#include <stdint.h>

// Problem dims (fixed by the reference setup)
#define BB 8
#define CC 512
#define LL 2048
#define NG 32
#define CPG 16

static const long long CL  = (long long)CC * LL;      // 1,048,576
static const long long LL2 = (long long)LL * LL;      // 4,194,304

// ---------------- scratch (device globals; no cudaMalloc allowed) ----------
__device__ float g_h [BB * CC * LL];             // gn out h [C][L]; later vT [L][C]
__device__ float g_ht[BB * CC * LL];             // qT [L][C]
__device__ float g_q [BB * CC * LL];             // q [C][L]; later h2T [L][C]
__device__ float g_k [BB * CC * LL];             // k [C][L]; later h2 [C][L]
__device__ float g_v [BB * CC * LL];             // v [C][L]
__device__ float g_s [(long long)BB * LL * LL];  // scores -> softmax P [L][L]
__device__ float g_w [4 * CC * CC];              // tf32 copies of wq,wk,wv,wo

__device__ __forceinline__ float f2tf32(float f) {
    uint32_t u;
    asm("cvt.rna.tf32.f32 %0, %1;" : "=r"(u) : "f"(f));
    return __uint_as_float(u);
}

// ---------------- weight tf32 conversion (one launch) ------------------------
__global__ void __launch_bounds__(256)
cvt4_kernel(const float4* __restrict__ a, const float4* __restrict__ b,
            const float4* __restrict__ c, const float4* __restrict__ d,
            float4* __restrict__ out)
{
    int i = blockIdx.x * 256 + threadIdx.x;       // 0 .. 262143
    int seg = i >> 16, off = i & 65535;
    const float4* src = (seg == 0) ? a : (seg == 1) ? b : (seg == 2) ? c : d;
    float4 v = src[off];
    v.x = f2tf32(v.x); v.y = f2tf32(v.y);
    v.z = f2tf32(v.z); v.w = f2tf32(v.w);
    out[i] = v;
}

// ---------------- GroupNorm (writes tf32-rounded output) ---------------------
__global__ void __launch_bounds__(256)
gn_kernel(const float* __restrict__ x, const float* __restrict__ gw,
          const float* __restrict__ gb, float* __restrict__ h)
{
    const int blk   = blockIdx.x;
    const int batch = blk >> 5;
    const int g     = blk & 31;
    const long long base = (long long)batch * CC * LL + (long long)g * CPG * LL;
    const float* xp = x + base;
    float*       hp = h + base;
    const int tid = threadIdx.x;
    const int NEL = CPG * LL;   // 32768

    float s = 0.f, ss = 0.f;
    for (int i = tid; i < NEL; i += 256) {
        float v = xp[i];
        s += v; ss += v * v;
    }
    __shared__ float rs[32], rss[32];
    #pragma unroll
    for (int o = 16; o; o >>= 1) {
        s  += __shfl_xor_sync(0xffffffffu, s,  o);
        ss += __shfl_xor_sync(0xffffffffu, ss, o);
    }
    const int warp = tid >> 5, lane = tid & 31;
    if (!lane) { rs[warp] = s; rss[warp] = ss; }
    __syncthreads();
    if (tid < 32) {
        float s2  = (tid < 8) ? rs[tid]  : 0.f;
        float ss2 = (tid < 8) ? rss[tid] : 0.f;
        #pragma unroll
        for (int o = 4; o; o >>= 1) {
            s2  += __shfl_xor_sync(0xffffffffu, s2,  o);
            ss2 += __shfl_xor_sync(0xffffffffu, ss2, o);
        }
        if (!tid) {
            float mean = s2 / (float)NEL;
            float var  = ss2 / (float)NEL - mean * mean;
            rs[0]  = mean;
            rss[0] = rsqrtf(var + 1e-6f);
        }
    }
    __syncthreads();
    const float mean = rs[0], inv = rss[0];
    for (int i = tid; i < NEL; i += 256) {
        int c = g * CPG + (i >> 11);
        hp[i] = f2tf32((xp[i] - mean) * inv * gw[c] + gb[c]);
    }
}

// ---------------- batched 32x32 tiled transpose ------------------------------
__global__ void __launch_bounds__(256)
transpose_kernel(const float* __restrict__ in, float* __restrict__ out,
                 int R, int Cd)
{
    __shared__ float tile[32][33];
    const long long zo = (long long)blockIdx.z * (long long)R * Cd;
    const int c0 = blockIdx.x * 32, r0 = blockIdx.y * 32;
    const int x = threadIdx.x & 31, y = threadIdx.x >> 5;

    #pragma unroll
    for (int i = 0; i < 4; i++)
        tile[y + 8 * i][x] = in[zo + (long long)(r0 + y + 8 * i) * Cd + c0 + x];
    __syncthreads();
    #pragma unroll
    for (int i = 0; i < 4; i++)
        out[zo + (long long)(c0 + y + 8 * i) * R + r0 + x] = tile[x][y + 8 * i];
}

// ---------------- tf32 mma.sync GEMM, 128x256 tile, 64x64 warp tile ----------
// 4-stage cp.async pipeline, one __syncthreads per k-step.
// C[m,n] = alpha * sum_k A[m*lda+k] * B[k*ldb+n] (+ bias[m]) (+ res[m*ldc+n])
// All operands MUST be tf32-pre-rounded. ROUND: tf32-round outputs.
#define BM 128
#define BN 256
#define BK 32
#define ASTR 36     // 36 mod 32 = 4 -> A frag banks = 4g + t (conflict-free)
#define BSTR 264    // 264 mod 32 = 8 -> B frag banks = 8t + g (conflict-free)
#define ASZ (BM * ASTR)            // 4608 floats
#define BSZ (BK * BSTR)            // 8448 floats
#define STAGE_F (ASZ + BSZ)        // 13056 floats = 52224 B
#define STAGES 4
#define GEMM_SMEM (STAGES * STAGE_F * 4)   // 208896 B

__device__ __forceinline__ void cp16(uint32_t dst, const float* src) {
    asm volatile("cp.async.ca.shared.global [%0], [%1], 16;" :: "r"(dst), "l"(src));
}

__device__ __forceinline__ void mma8(float* c, const uint32_t* a, const uint32_t* b) {
    asm volatile(
        "mma.sync.aligned.m16n8k8.row.col.f32.tf32.tf32.f32 "
        "{%0,%1,%2,%3}, {%4,%5,%6,%7}, {%8,%9}, {%0,%1,%2,%3};"
        : "+f"(c[0]), "+f"(c[1]), "+f"(c[2]), "+f"(c[3])
        : "r"(a[0]), "r"(a[1]), "r"(a[2]), "r"(a[3]), "r"(b[0]), "r"(b[1]));
}

template<bool ROUND>
__global__ void __launch_bounds__(256, 1)
gemm_tf32_nn(const float* __restrict__ A, long long sA,
             const float* __restrict__ B, long long sB,
             const float* __restrict__ bias,
             const float* __restrict__ res, long long sRes,
             float* __restrict__ C, long long sC,
             int K, int lda, int ldb, int ldc, float alpha)
{
    extern __shared__ float smf[];   // STAGES x [A(128x36) | B(32x264)]

    const int z = blockIdx.z;
    A += (long long)z * sA;
    B += (long long)z * sB;
    C += (long long)z * sC;
    const float* R = res ? res + (long long)z * sRes : nullptr;

    const int bm = blockIdx.y * BM;
    const int bn = blockIdx.x * BN;
    const int tid  = threadIdx.x;
    const int warp = tid >> 5, lane = tid & 31;
    const int wm = warp >> 2, wn = warp & 3;   // 2x4 warp grid, 64x64 each
    const int g  = lane >> 2, t  = lane & 3;

    const int a_kq = tid & 7,  a_m = tid >> 3;   // A fill: 8 k-quads x 32 rows
    const int b_nq = tid & 63, b_k = tid >> 6;   // B fill: 64 n-quads x 4 k rows

    const uint32_t sm_u = (uint32_t)__cvta_generic_to_shared(smf);

    float acc[4][8][4];
    #pragma unroll
    for (int i = 0; i < 4; i++)
        #pragma unroll
        for (int j = 0; j < 8; j++)
            #pragma unroll
            for (int q = 0; q < 4; q++) acc[i][j][q] = 0.f;

    auto fill = [&](int stg, int k0) {
        const uint32_t ab = sm_u + (uint32_t)(stg * STAGE_F * 4);
        const uint32_t bb = ab + (uint32_t)(ASZ * 4);
        #pragma unroll
        for (int mi = 0; mi < 4; mi++) {
            const int row = a_m + 32 * mi;
            cp16(ab + (uint32_t)((row * ASTR + a_kq * 4) * 4),
                 A + (long long)(bm + row) * lda + k0 + a_kq * 4);
        }
        #pragma unroll
        for (int ki = 0; ki < 8; ki++) {
            const int k = b_k + 4 * ki;
            cp16(bb + (uint32_t)((k * BSTR + b_nq * 4) * 4),
                 B + (long long)(k0 + k) * ldb + bn + b_nq * 4);
        }
        asm volatile("cp.async.commit_group;" ::: "memory");
    };

    const int nk = K / BK;      // 16 or 64 (always >= STAGES here)
    fill(0, 0);
    fill(1, BK);
    fill(2, 2 * BK);

    for (int ks = 0; ks < nk; ks++) {
        const int cur = ks & 3;
        const int rem = nk - 1 - ks;     // groups committed after stage ks
        if (rem >= 2)      asm volatile("cp.async.wait_group 2;" ::: "memory");
        else if (rem == 1) asm volatile("cp.async.wait_group 1;" ::: "memory");
        else               asm volatile("cp.async.wait_group 0;" ::: "memory");
        __syncthreads();

        if (ks + 3 < nk) fill((ks + 3) & 3, (ks + 3) * BK);

        const uint32_t* Ab = (const uint32_t*)(smf + cur * STAGE_F);
        const uint32_t* Bb = (const uint32_t*)(smf + cur * STAGE_F + ASZ);

        #pragma unroll
        for (int k8 = 0; k8 < 4; k8++) {
            const int kk = k8 * 8;
            uint32_t bf[8][2];
            #pragma unroll
            for (int nt = 0; nt < 8; nt++) {
                const int col = wn * 64 + nt * 8 + g;
                bf[nt][0] = Bb[(kk + t) * BSTR + col];
                bf[nt][1] = Bb[(kk + t + 4) * BSTR + col];
            }
            #pragma unroll
            for (int mt = 0; mt < 4; mt++) {
                const int row = wm * 64 + mt * 16 + g;
                uint32_t af[4];
                af[0] = Ab[row * ASTR + kk + t];
                af[1] = Ab[(row + 8) * ASTR + kk + t];
                af[2] = Ab[row * ASTR + kk + t + 4];
                af[3] = Ab[(row + 8) * ASTR + kk + t + 4];
                #pragma unroll
                for (int nt = 0; nt < 8; nt++)
                    mma8(acc[mt][nt], af, bf[nt]);
            }
        }
    }

    // epilogue: c0:(g,2t) c1:(g,2t+1) c2:(g+8,2t) c3:(g+8,2t+1)
    #pragma unroll
    for (int mt = 0; mt < 4; mt++) {
        const int r0 = bm + wm * 64 + mt * 16 + g;
        const float bi0 = bias ? bias[r0]     : 0.f;
        const float bi1 = bias ? bias[r0 + 8] : 0.f;
        #pragma unroll
        for (int nt = 0; nt < 8; nt++) {
            const int c0 = bn + wn * 64 + nt * 8 + 2 * t;
            float2 v0, v1;
            v0.x = acc[mt][nt][0] * alpha + bi0;
            v0.y = acc[mt][nt][1] * alpha + bi0;
            v1.x = acc[mt][nt][2] * alpha + bi1;
            v1.y = acc[mt][nt][3] * alpha + bi1;
            if (R) {
                const float2 r0v = *(const float2*)&R[(long long)r0 * ldc + c0];
                const float2 r1v = *(const float2*)&R[(long long)(r0 + 8) * ldc + c0];
                v0.x += r0v.x; v0.y += r0v.y;
                v1.x += r1v.x; v1.y += r1v.y;
            }
            if (ROUND) {
                v0.x = f2tf32(v0.x); v0.y = f2tf32(v0.y);
                v1.x = f2tf32(v1.x); v1.y = f2tf32(v1.y);
            }
            *(float2*)&C[(long long)r0 * ldc + c0]       = v0;
            *(float2*)&C[(long long)(r0 + 8) * ldc + c0] = v1;
        }
    }
}

// ---------------- row softmax (writes tf32-rounded P) ------------------------
__global__ void __launch_bounds__(256)
softmax_kernel(float* __restrict__ sm)
{
    float* row = sm + (long long)blockIdx.x * LL;
    const int tid = threadIdx.x;
    const int warp = tid >> 5, lane = tid & 31;

    float v[8];
    float mx = -1e30f;
    #pragma unroll
    for (int i = 0; i < 8; i++) {
        v[i] = row[tid + 256 * i];
        mx = fmaxf(mx, v[i]);
    }
    __shared__ float red[32];
    __shared__ float bcast;
    #pragma unroll
    for (int o = 16; o; o >>= 1) mx = fmaxf(mx, __shfl_xor_sync(0xffffffffu, mx, o));
    if (!lane) red[warp] = mx;
    __syncthreads();
    if (tid < 32) {
        float m2 = (tid < 8) ? red[tid] : -1e30f;
        #pragma unroll
        for (int o = 4; o; o >>= 1) m2 = fmaxf(m2, __shfl_xor_sync(0xffffffffu, m2, o));
        if (!tid) bcast = m2;
    }
    __syncthreads();
    mx = bcast;

    float s = 0.f;
    #pragma unroll
    for (int i = 0; i < 8; i++) {
        v[i] = expf(v[i] - mx);
        s += v[i];
    }
    #pragma unroll
    for (int o = 16; o; o >>= 1) s += __shfl_xor_sync(0xffffffffu, s, o);
    if (!lane) red[warp] = s;
    __syncthreads();
    if (tid < 32) {
        float s2 = (tid < 8) ? red[tid] : 0.f;
        #pragma unroll
        for (int o = 4; o; o >>= 1) s2 += __shfl_xor_sync(0xffffffffu, s2, o);
        if (!tid) bcast = s2;
    }
    __syncthreads();
    const float inv = 1.f / bcast;
    #pragma unroll
    for (int i = 0; i < 8; i++) row[tid + 256 * i] = f2tf32(v[i] * inv);
}

// ---------------- launch ------------------------------------------------------
extern "C" void kernel_launch(void* const* d_in, const int* in_sizes, int n_in,
                              void* d_out, int out_size)
{
    const float* x  = (const float*)d_in[0];
    const float* gw = (const float*)d_in[1];
    const float* gb = (const float*)d_in[2];
    const float* wq = (const float*)d_in[3];
    const float* bq = (const float*)d_in[4];
    const float* wk = (const float*)d_in[5];
    const float* bk = (const float*)d_in[6];
    const float* wv = (const float*)d_in[7];
    const float* bv = (const float*)d_in[8];
    const float* wo = (const float*)d_in[9];
    const float* bo = (const float*)d_in[10];
    float* out = (float*)d_out;

    float *h, *ht, *q, *k, *v, *s, *w;
    cudaGetSymbolAddress((void**)&h,  g_h);
    cudaGetSymbolAddress((void**)&ht, g_ht);
    cudaGetSymbolAddress((void**)&q,  g_q);
    cudaGetSymbolAddress((void**)&k,  g_k);
    cudaGetSymbolAddress((void**)&v,  g_v);
    cudaGetSymbolAddress((void**)&s,  g_s);
    cudaGetSymbolAddress((void**)&w,  g_w);

    float* wqt = w;
    float* wkt = w + CC * CC;
    float* wvt = w + 2 * CC * CC;
    float* wot = w + 3 * CC * CC;

    cudaFuncSetAttribute(gemm_tf32_nn<true>,
                         cudaFuncAttributeMaxDynamicSharedMemorySize, GEMM_SMEM);
    cudaFuncSetAttribute(gemm_tf32_nn<false>,
                         cudaFuncAttributeMaxDynamicSharedMemorySize, GEMM_SMEM);

    const float scale = 0.044194173824159216f;   // 512^-0.5
    dim3 blk(256);

    // 0) tf32 copies of all weights
    cvt4_kernel<<<1024, 256>>>((const float4*)wq, (const float4*)wk,
                               (const float4*)wv, (const float4*)wo, (float4*)w);

    // 1) GroupNorm -> h [C][L] (tf32)
    gn_kernel<<<BB * NG, 256>>>(x, gw, gb, h);

    // 2) Q/K/V = W @ H_b + bias  (M=C, N=L, K=C; tf32-rounded outs)
    dim3 gQKV(LL / BN, CC / BM, BB);     // (8,4,8)
    gemm_tf32_nn<true><<<gQKV, blk, GEMM_SMEM>>>(
        wqt, 0LL, h, CL, bq, nullptr, 0LL, q, CL, CC, CC, LL, LL, 1.f);
    gemm_tf32_nn<true><<<gQKV, blk, GEMM_SMEM>>>(
        wkt, 0LL, h, CL, bk, nullptr, 0LL, k, CL, CC, CC, LL, LL, 1.f);
    gemm_tf32_nn<true><<<gQKV, blk, GEMM_SMEM>>>(
        wvt, 0LL, h, CL, bv, nullptr, 0LL, v, CL, CC, CC, LL, LL, 1.f);

    // 3) qT [L][C] into g_ht
    transpose_kernel<<<dim3(LL / 32, CC / 32, BB), 256>>>(q, ht, CC, LL);

    // 4) S = scale * qT @ k  (M=L, N=L, K=C; fp32 scores out)
    dim3 gS(LL / BN, LL / BM, BB);       // (8,16,8)
    gemm_tf32_nn<false><<<gS, blk, GEMM_SMEM>>>(
        ht, CL, k, CL, nullptr, nullptr, 0LL, s, LL2, CC, CC, LL, LL, scale);

    // 5) row softmax (tf32-rounded P)
    softmax_kernel<<<BB * LL, 256>>>(s);

    // 6) vT [L][C] into g_h (h dead after QKV)
    transpose_kernel<<<dim3(LL / 32, CC / 32, BB), 256>>>(v, h, CC, LL);

    // 7) h2T = P @ vT  (M=L, N=C, K=L; lda=LL for P!) into g_q (q dead)
    dim3 gA(CC / BN, LL / BM, BB);       // (2,16,8)
    gemm_tf32_nn<true><<<gA, blk, GEMM_SMEM>>>(
        s, LL2, h, CL, nullptr, nullptr, 0LL, q, CL, LL, LL, CC, CC, 1.f);

    // 8) h2 [C][L] into g_k (k dead after scores)
    transpose_kernel<<<dim3(CC / 32, LL / 32, BB), 256>>>(q, k, LL, CC);

    // 9) out = x + wo @ h2 + bo  (M=C, N=L, K=C; fp32 out)
    dim3 gO(LL / BN, CC / BM, BB);       // (8,4,8)
    gemm_tf32_nn<false><<<gO, blk, GEMM_SMEM>>>(
        wot, 0LL, k, CL, bo, x, CL, out, CL, CC, CC, LL, LL, 1.f);
}

// round 12
// speedup vs baseline: 1.2239x; 1.2239x over previous
#include <cuda_runtime.h>
#include <math.h>
#include <stdint.h>

// Problem dims (fixed by the reference setup)
#define BB 8
#define CC 512
#define LL 2048
#define NG 32
#define CPG 16

static const long long CL  = (long long)CC * LL;      // 1,048,576
static const long long LL2 = (long long)LL * LL;      // 4,194,304

// ---------------- scratch (device globals; no cudaMalloc allowed) ----------
__device__ float g_h [BB * CC * LL];             // gn out h [C][L]; later vT [L][C]
__device__ float g_ht[BB * CC * LL];             // qT [L][C]
__device__ float g_q [BB * CC * LL];             // q [C][L]; later h2T [L][C]
__device__ float g_k [BB * CC * LL];             // k [C][L]; later h2 [C][L]
__device__ float g_v [BB * CC * LL];             // v [C][L]
__device__ float g_s [(long long)BB * LL * LL];  // scores -> softmax P [L][L]
__device__ float g_w [4 * CC * CC];              // tf32 copies of wq,wk,wv,wo

__device__ __forceinline__ float f2tf32(float f) {
    uint32_t u;
    asm("cvt.rna.tf32.f32 %0, %1;" : "=r"(u) : "f"(f));
    return __uint_as_float(u);
}

// ---------------- weight tf32 conversion (one launch) ------------------------
__global__ void __launch_bounds__(256)
cvt4_kernel(const float4* __restrict__ a, const float4* __restrict__ b,
            const float4* __restrict__ c, const float4* __restrict__ d,
            float4* __restrict__ out)
{
    int i = blockIdx.x * 256 + threadIdx.x;       // 0 .. 262143
    int seg = i >> 16, off = i & 65535;
    const float4* src = (seg == 0) ? a : (seg == 1) ? b : (seg == 2) ? c : d;
    float4 v = src[off];
    v.x = f2tf32(v.x); v.y = f2tf32(v.y);
    v.z = f2tf32(v.z); v.w = f2tf32(v.w);
    out[i] = v;
}

// ---------------- GroupNorm (writes tf32-rounded output) ---------------------
__global__ void __launch_bounds__(256)
gn_kernel(const float* __restrict__ x, const float* __restrict__ gw,
          const float* __restrict__ gb, float* __restrict__ h)
{
    const int blk   = blockIdx.x;
    const int batch = blk >> 5;
    const int g     = blk & 31;
    const long long base = (long long)batch * CC * LL + (long long)g * CPG * LL;
    const float* xp = x + base;
    float*       hp = h + base;
    const int tid = threadIdx.x;
    const int NEL = CPG * LL;   // 32768

    float s = 0.f, ss = 0.f;
    for (int i = tid; i < NEL; i += 256) {
        float v = xp[i];
        s += v; ss += v * v;
    }
    __shared__ float rs[32], rss[32];
    #pragma unroll
    for (int o = 16; o; o >>= 1) {
        s  += __shfl_xor_sync(0xffffffffu, s,  o);
        ss += __shfl_xor_sync(0xffffffffu, ss, o);
    }
    const int warp = tid >> 5, lane = tid & 31;
    if (!lane) { rs[warp] = s; rss[warp] = ss; }
    __syncthreads();
    if (tid < 32) {
        float s2  = (tid < 8) ? rs[tid]  : 0.f;
        float ss2 = (tid < 8) ? rss[tid] : 0.f;
        #pragma unroll
        for (int o = 4; o; o >>= 1) {
            s2  += __shfl_xor_sync(0xffffffffu, s2,  o);
            ss2 += __shfl_xor_sync(0xffffffffu, ss2, o);
        }
        if (!tid) {
            float mean = s2 / (float)NEL;
            float var  = ss2 / (float)NEL - mean * mean;
            rs[0]  = mean;
            rss[0] = rsqrtf(var + 1e-6f);
        }
    }
    __syncthreads();
    const float mean = rs[0], inv = rss[0];
    for (int i = tid; i < NEL; i += 256) {
        int c = g * CPG + (i >> 11);
        hp[i] = f2tf32((xp[i] - mean) * inv * gw[c] + gb[c]);
    }
}

// ---------------- batched 32x32 tiled transpose ------------------------------
__global__ void __launch_bounds__(256)
transpose_kernel(const float* __restrict__ in, float* __restrict__ out,
                 int R, int Cd)
{
    __shared__ float tile[32][33];
    const long long zo = (long long)blockIdx.z * (long long)R * Cd;
    const int c0 = blockIdx.x * 32, r0 = blockIdx.y * 32;
    const int x = threadIdx.x & 31, y = threadIdx.x >> 5;

    #pragma unroll
    for (int i = 0; i < 4; i++)
        tile[y + 8 * i][x] = in[zo + (long long)(r0 + y + 8 * i) * Cd + c0 + x];
    __syncthreads();
    #pragma unroll
    for (int i = 0; i < 4; i++)
        out[zo + (long long)(c0 + y + 8 * i) * R + r0 + x] = tile[x][y + 8 * i];
}

// ---------------- tf32 mma.sync GEMM, 128x256 tile, 64x64 warp tile ----------
// 2-stage smem double buffer + 2-deep register fragment pipeline.
// C[m,n] = alpha * sum_k A[m*lda+k] * B[k*ldb+n] (+ bias[m]) (+ res[m*ldc+n])
// All operands MUST be tf32-pre-rounded. ROUND: tf32-round outputs.
#define BM 128
#define BN 256
#define BK 32
#define ASTR 36     // 36 mod 32 = 4 -> A frag banks = 4g + t (conflict-free)
#define BSTR 264    // 264 mod 32 = 8 -> B frag banks = 8t + g (conflict-free)
#define ASZ (BM * ASTR)     // 4608 floats
#define BSZ (BK * BSTR)     // 8448 floats
#define GEMM_SMEM ((2 * ASZ + 2 * BSZ) * 4)   // 104448 B

__device__ __forceinline__ void cp16(uint32_t dst, const float* src) {
    asm volatile("cp.async.ca.shared.global [%0], [%1], 16;" :: "r"(dst), "l"(src));
}

__device__ __forceinline__ void mma8(float* c, const uint32_t* a, const uint32_t* b) {
    asm volatile(
        "mma.sync.aligned.m16n8k8.row.col.f32.tf32.tf32.f32 "
        "{%0,%1,%2,%3}, {%4,%5,%6,%7}, {%8,%9}, {%0,%1,%2,%3};"
        : "+f"(c[0]), "+f"(c[1]), "+f"(c[2]), "+f"(c[3])
        : "r"(a[0]), "r"(a[1]), "r"(a[2]), "r"(a[3]), "r"(b[0]), "r"(b[1]));
}

template<bool ROUND>
__global__ void __launch_bounds__(256, 1)
gemm_tf32_nn(const float* __restrict__ A, long long sA,
             const float* __restrict__ B, long long sB,
             const float* __restrict__ bias,
             const float* __restrict__ res, long long sRes,
             float* __restrict__ C, long long sC,
             int K, int lda, int ldb, int ldc, float alpha)
{
    extern __shared__ float smf[];
    float* As = smf;                 // 2 buffers of [128][36]
    float* Bs = smf + 2 * ASZ;       // 2 buffers of [32][264]

    const int z = blockIdx.z;
    A += (long long)z * sA;
    B += (long long)z * sB;
    C += (long long)z * sC;
    const float* R = res ? res + (long long)z * sRes : nullptr;

    const int bm = blockIdx.y * BM;
    const int bn = blockIdx.x * BN;
    const int tid  = threadIdx.x;
    const int warp = tid >> 5, lane = tid & 31;
    const int wm = warp >> 2, wn = warp & 3;   // 2x4 warp grid, 64x64 each
    const int g  = lane >> 2, t  = lane & 3;

    const int a_kq = tid & 7,  a_m = tid >> 3;   // A fill: 8 k-quads x 32 rows
    const int b_nq = tid & 63, b_k = tid >> 6;   // B fill: 64 n-quads x 4 k rows

    const uint32_t as_u = (uint32_t)__cvta_generic_to_shared(As);
    const uint32_t bs_u = (uint32_t)__cvta_generic_to_shared(Bs);

    float acc[4][8][4];
    #pragma unroll
    for (int i = 0; i < 4; i++)
        #pragma unroll
        for (int j = 0; j < 8; j++)
            #pragma unroll
            for (int q = 0; q < 4; q++) acc[i][j][q] = 0.f;

    auto fill = [&](int buf, int k0) {
        const uint32_t ab = as_u + (uint32_t)(buf * ASZ * 4);
        const uint32_t bb = bs_u + (uint32_t)(buf * BSZ * 4);
        #pragma unroll
        for (int mi = 0; mi < 4; mi++) {
            const int row = a_m + 32 * mi;
            cp16(ab + (uint32_t)((row * ASTR + a_kq * 4) * 4),
                 A + (long long)(bm + row) * lda + k0 + a_kq * 4);
        }
        #pragma unroll
        for (int ki = 0; ki < 8; ki++) {
            const int k = b_k + 4 * ki;
            cp16(bb + (uint32_t)((k * BSTR + b_nq * 4) * 4),
                 B + (long long)(k0 + k) * ldb + bn + b_nq * 4);
        }
        asm volatile("cp.async.commit_group;" ::: "memory");
    };

    const int nk = K / BK;
    fill(0, 0);
    int buf = 0;

    for (int ks = 0; ks < nk; ks++) {
        if (ks + 1 < nk) {
            fill(buf ^ 1, (ks + 1) * BK);
            asm volatile("cp.async.wait_group 1;" ::: "memory");
        } else {
            asm volatile("cp.async.wait_group 0;" ::: "memory");
        }
        __syncthreads();

        const uint32_t* Ab = (const uint32_t*)(As + buf * ASZ);
        const uint32_t* Bb = (const uint32_t*)(Bs + buf * BSZ);

        // register fragment pipeline: 2-deep (current / next k8)
        uint32_t af[2][4][4], bf[2][8][2];

        // preload k8 = 0 into slot 0
        #pragma unroll
        for (int nt = 0; nt < 8; nt++) {
            const int col = wn * 64 + nt * 8 + g;
            bf[0][nt][0] = Bb[t * BSTR + col];
            bf[0][nt][1] = Bb[(t + 4) * BSTR + col];
        }
        #pragma unroll
        for (int mt = 0; mt < 4; mt++) {
            const int row = wm * 64 + mt * 16 + g;
            af[0][mt][0] = Ab[row * ASTR + t];
            af[0][mt][1] = Ab[(row + 8) * ASTR + t];
            af[0][mt][2] = Ab[row * ASTR + t + 4];
            af[0][mt][3] = Ab[(row + 8) * ASTR + t + 4];
        }

        #pragma unroll
        for (int k8 = 0; k8 < 4; k8++) {
            const int c = k8 & 1, nx = c ^ 1;
            if (k8 < 3) {
                const int kk = (k8 + 1) * 8;
                #pragma unroll
                for (int nt = 0; nt < 8; nt++) {
                    const int col = wn * 64 + nt * 8 + g;
                    bf[nx][nt][0] = Bb[(kk + t) * BSTR + col];
                    bf[nx][nt][1] = Bb[(kk + t + 4) * BSTR + col];
                }
                #pragma unroll
                for (int mt = 0; mt < 4; mt++) {
                    const int row = wm * 64 + mt * 16 + g;
                    af[nx][mt][0] = Ab[row * ASTR + kk + t];
                    af[nx][mt][1] = Ab[(row + 8) * ASTR + kk + t];
                    af[nx][mt][2] = Ab[row * ASTR + kk + t + 4];
                    af[nx][mt][3] = Ab[(row + 8) * ASTR + kk + t + 4];
                }
            }
            #pragma unroll
            for (int mt = 0; mt < 4; mt++)
                #pragma unroll
                for (int nt = 0; nt < 8; nt++)
                    mma8(acc[mt][nt], af[c][mt], bf[c][nt]);
        }
        __syncthreads();
        buf ^= 1;
    }

    // epilogue: c0:(g,2t) c1:(g,2t+1) c2:(g+8,2t) c3:(g+8,2t+1)
    #pragma unroll
    for (int mt = 0; mt < 4; mt++) {
        const int r0 = bm + wm * 64 + mt * 16 + g;
        const float bi0 = bias ? bias[r0]     : 0.f;
        const float bi1 = bias ? bias[r0 + 8] : 0.f;
        #pragma unroll
        for (int nt = 0; nt < 8; nt++) {
            const int c0 = bn + wn * 64 + nt * 8 + 2 * t;
            float2 v0, v1;
            v0.x = acc[mt][nt][0] * alpha + bi0;
            v0.y = acc[mt][nt][1] * alpha + bi0;
            v1.x = acc[mt][nt][2] * alpha + bi1;
            v1.y = acc[mt][nt][3] * alpha + bi1;
            if (R) {
                const float2 r0v = *(const float2*)&R[(long long)r0 * ldc + c0];
                const float2 r1v = *(const float2*)&R[(long long)(r0 + 8) * ldc + c0];
                v0.x += r0v.x; v0.y += r0v.y;
                v1.x += r1v.x; v1.y += r1v.y;
            }
            if (ROUND) {
                v0.x = f2tf32(v0.x); v0.y = f2tf32(v0.y);
                v1.x = f2tf32(v1.x); v1.y = f2tf32(v1.y);
            }
            *(float2*)&C[(long long)r0 * ldc + c0]       = v0;
            *(float2*)&C[(long long)(r0 + 8) * ldc + c0] = v1;
        }
    }
}

// ---------------- row softmax (writes tf32-rounded P) ------------------------
__global__ void __launch_bounds__(256)
softmax_kernel(float* __restrict__ sm)
{
    float* row = sm + (long long)blockIdx.x * LL;
    const int tid = threadIdx.x;
    const int warp = tid >> 5, lane = tid & 31;

    float v[8];
    float mx = -1e30f;
    #pragma unroll
    for (int i = 0; i < 8; i++) {
        v[i] = row[tid + 256 * i];
        mx = fmaxf(mx, v[i]);
    }
    __shared__ float red[32];
    __shared__ float bcast;
    #pragma unroll
    for (int o = 16; o; o >>= 1) mx = fmaxf(mx, __shfl_xor_sync(0xffffffffu, mx, o));
    if (!lane) red[warp] = mx;
    __syncthreads();
    if (tid < 32) {
        float m2 = (tid < 8) ? red[tid] : -1e30f;
        #pragma unroll
        for (int o = 4; o; o >>= 1) m2 = fmaxf(m2, __shfl_xor_sync(0xffffffffu, m2, o));
        if (!tid) bcast = m2;
    }
    __syncthreads();
    mx = bcast;

    float s = 0.f;
    #pragma unroll
    for (int i = 0; i < 8; i++) {
        v[i] = expf(v[i] - mx);
        s += v[i];
    }
    #pragma unroll
    for (int o = 16; o; o >>= 1) s += __shfl_xor_sync(0xffffffffu, s, o);
    if (!lane) red[warp] = s;
    __syncthreads();
    if (tid < 32) {
        float s2 = (tid < 8) ? red[tid] : 0.f;
        #pragma unroll
        for (int o = 4; o; o >>= 1) s2 += __shfl_xor_sync(0xffffffffu, s2, o);
        if (!tid) bcast = s2;
    }
    __syncthreads();
    const float inv = 1.f / bcast;
    #pragma unroll
    for (int i = 0; i < 8; i++) row[tid + 256 * i] = f2tf32(v[i] * inv);
}

// ---------------- launch ------------------------------------------------------
extern "C" void kernel_launch(void* const* d_in, const int* in_sizes, int n_in,
                              void* d_out, int out_size)
{
    const float* x  = (const float*)d_in[0];
    const float* gw = (const float*)d_in[1];
    const float* gb = (const float*)d_in[2];
    const float* wq = (const float*)d_in[3];
    const float* bq = (const float*)d_in[4];
    const float* wk = (const float*)d_in[5];
    const float* bk = (const float*)d_in[6];
    const float* wv = (const float*)d_in[7];
    const float* bv = (const float*)d_in[8];
    const float* wo = (const float*)d_in[9];
    const float* bo = (const float*)d_in[10];
    float* out = (float*)d_out;

    float *h, *ht, *q, *k, *v, *s, *w;
    cudaGetSymbolAddress((void**)&h,  g_h);
    cudaGetSymbolAddress((void**)&ht, g_ht);
    cudaGetSymbolAddress((void**)&q,  g_q);
    cudaGetSymbolAddress((void**)&k,  g_k);
    cudaGetSymbolAddress((void**)&v,  g_v);
    cudaGetSymbolAddress((void**)&s,  g_s);
    cudaGetSymbolAddress((void**)&w,  g_w);

    float* wqt = w;
    float* wkt = w + CC * CC;
    float* wvt = w + 2 * CC * CC;
    float* wot = w + 3 * CC * CC;

    cudaFuncSetAttribute(gemm_tf32_nn<true>,
                         cudaFuncAttributeMaxDynamicSharedMemorySize, GEMM_SMEM);
    cudaFuncSetAttribute(gemm_tf32_nn<false>,
                         cudaFuncAttributeMaxDynamicSharedMemorySize, GEMM_SMEM);

    const float scale = 0.044194173824159216f;   // 512^-0.5
    dim3 blk(256);

    // 0) tf32 copies of all weights
    cvt4_kernel<<<1024, 256>>>((const float4*)wq, (const float4*)wk,
                               (const float4*)wv, (const float4*)wo, (float4*)w);

    // 1) GroupNorm -> h [C][L] (tf32)
    gn_kernel<<<BB * NG, 256>>>(x, gw, gb, h);

    // 2) Q/K/V = W @ H_b + bias  (M=C, N=L, K=C; tf32-rounded outs)
    dim3 gQKV(LL / BN, CC / BM, BB);     // (8,4,8)
    gemm_tf32_nn<true><<<gQKV, blk, GEMM_SMEM>>>(
        wqt, 0LL, h, CL, bq, nullptr, 0LL, q, CL, CC, CC, LL, LL, 1.f);
    gemm_tf32_nn<true><<<gQKV, blk, GEMM_SMEM>>>(
        wkt, 0LL, h, CL, bk, nullptr, 0LL, k, CL, CC, CC, LL, LL, 1.f);
    gemm_tf32_nn<true><<<gQKV, blk, GEMM_SMEM>>>(
        wvt, 0LL, h, CL, bv, nullptr, 0LL, v, CL, CC, CC, LL, LL, 1.f);

    // 3) qT [L][C] into g_ht
    transpose_kernel<<<dim3(LL / 32, CC / 32, BB), 256>>>(q, ht, CC, LL);

    // 4) S = scale * qT @ k  (M=L, N=L, K=C; fp32 scores out)
    dim3 gS(LL / BN, LL / BM, BB);       // (8,16,8)
    gemm_tf32_nn<false><<<gS, blk, GEMM_SMEM>>>(
        ht, CL, k, CL, nullptr, nullptr, 0LL, s, LL2, CC, CC, LL, LL, scale);

    // 5) row softmax (tf32-rounded P)
    softmax_kernel<<<BB * LL, 256>>>(s);

    // 6) vT [L][C] into g_h (h dead after QKV)
    transpose_kernel<<<dim3(LL / 32, CC / 32, BB), 256>>>(v, h, CC, LL);

    // 7) h2T = P @ vT  (M=L, N=C, K=L; lda=LL for P!) into g_q (q dead)
    dim3 gA(CC / BN, LL / BM, BB);       // (2,16,8)
    gemm_tf32_nn<true><<<gA, blk, GEMM_SMEM>>>(
        s, LL2, h, CL, nullptr, nullptr, 0LL, q, CL, LL, LL, CC, CC, 1.f);

    // 8) h2 [C][L] into g_k (k dead after scores)
    transpose_kernel<<<dim3(CC / 32, LL / 32, BB), 256>>>(q, k, LL, CC);

    // 9) out = x + wo @ h2 + bo  (M=C, N=L, K=C; fp32 out)
    dim3 gO(LL / BN, CC / BM, BB);       // (8,4,8)
    gemm_tf32_nn<false><<<gO, blk, GEMM_SMEM>>>(
        wot, 0LL, k, CL, bo, x, CL, out, CL, CC, CC, LL, LL, 1.f);
}

// round 13
// speedup vs baseline: 1.2546x; 1.0252x over previous
#include <cuda_runtime.h>
#include <math.h>
#include <stdint.h>

// Problem dims (fixed by the reference setup)
#define BB 8
#define CC 512
#define LL 2048
#define NG 32
#define CPG 16

static const long long CL  = (long long)CC * LL;      // 1,048,576
static const long long C3L = 3LL * CC * LL;           // 3,145,728
static const long long LL2 = (long long)LL * LL;      // 4,194,304

// ---------------- scratch (device globals; no cudaMalloc allowed) ----------
__device__ float g_h  [BB * CC * LL];              // gn out h [C][L]; later vT [L][C]
__device__ float g_ht [BB * CC * LL];              // qT [L][C]; later h2 [C][L]
__device__ float g_qkv[BB * 3 * CC * LL];          // fused q/k/v [3C][L] per batch
__device__ float g_h2 [BB * CC * LL];              // h2T [L][C]
__device__ float g_s  [(long long)BB * LL * LL];   // scores -> softmax P [L][L]
__device__ float g_w  [4 * CC * CC];               // tf32 wq,wk,wv,wo (contiguous)
__device__ float g_bc [3 * CC];                    // concat bq,bk,bv

__device__ __forceinline__ float f2tf32(float f) {
    uint32_t u;
    asm("cvt.rna.tf32.f32 %0, %1;" : "=r"(u) : "f"(f));
    return __uint_as_float(u);
}

// ---------------- weight tf32 conversion (one launch) ------------------------
__global__ void __launch_bounds__(256)
cvt4_kernel(const float4* __restrict__ a, const float4* __restrict__ b,
            const float4* __restrict__ c, const float4* __restrict__ d,
            float4* __restrict__ out)
{
    int i = blockIdx.x * 256 + threadIdx.x;       // 0 .. 262143
    int seg = i >> 16, off = i & 65535;
    const float4* src = (seg == 0) ? a : (seg == 1) ? b : (seg == 2) ? c : d;
    float4 v = src[off];
    v.x = f2tf32(v.x); v.y = f2tf32(v.y);
    v.z = f2tf32(v.z); v.w = f2tf32(v.w);
    out[i] = v;
}

// ---------------- bias concat (bq|bk|bv) --------------------------------------
__global__ void __launch_bounds__(256)
bcat_kernel(const float* __restrict__ bq, const float* __restrict__ bk,
            const float* __restrict__ bv, float* __restrict__ out)
{
    int i = blockIdx.x * 256 + threadIdx.x;       // 0..1535
    if (i < CC)            out[i] = bq[i];
    else if (i < 2 * CC)   out[i] = bk[i - CC];
    else if (i < 3 * CC)   out[i] = bv[i - 2 * CC];
}

// ---------------- GroupNorm (writes tf32-rounded output) ---------------------
__global__ void __launch_bounds__(256)
gn_kernel(const float* __restrict__ x, const float* __restrict__ gw,
          const float* __restrict__ gb, float* __restrict__ h)
{
    const int blk   = blockIdx.x;
    const int batch = blk >> 5;
    const int g     = blk & 31;
    const long long base = (long long)batch * CC * LL + (long long)g * CPG * LL;
    const float* xp = x + base;
    float*       hp = h + base;
    const int tid = threadIdx.x;
    const int NEL = CPG * LL;   // 32768

    float s = 0.f, ss = 0.f;
    for (int i = tid; i < NEL; i += 256) {
        float v = xp[i];
        s += v; ss += v * v;
    }
    __shared__ float rs[32], rss[32];
    #pragma unroll
    for (int o = 16; o; o >>= 1) {
        s  += __shfl_xor_sync(0xffffffffu, s,  o);
        ss += __shfl_xor_sync(0xffffffffu, ss, o);
    }
    const int warp = tid >> 5, lane = tid & 31;
    if (!lane) { rs[warp] = s; rss[warp] = ss; }
    __syncthreads();
    if (tid < 32) {
        float s2  = (tid < 8) ? rs[tid]  : 0.f;
        float ss2 = (tid < 8) ? rss[tid] : 0.f;
        #pragma unroll
        for (int o = 4; o; o >>= 1) {
            s2  += __shfl_xor_sync(0xffffffffu, s2,  o);
            ss2 += __shfl_xor_sync(0xffffffffu, ss2, o);
        }
        if (!tid) {
            float mean = s2 / (float)NEL;
            float var  = ss2 / (float)NEL - mean * mean;
            rs[0]  = mean;
            rss[0] = rsqrtf(var + 1e-6f);
        }
    }
    __syncthreads();
    const float mean = rs[0], inv = rss[0];
    for (int i = tid; i < NEL; i += 256) {
        int c = g * CPG + (i >> 11);
        hp[i] = f2tf32((xp[i] - mean) * inv * gw[c] + gb[c]);
    }
}

// ---------------- batched 32x32 tiled transpose (with batch strides) ---------
__global__ void __launch_bounds__(256)
transpose_kernel(const float* __restrict__ in, long long sIn,
                 float* __restrict__ out, long long sOut,
                 int R, int Cd)
{
    __shared__ float tile[32][33];
    const float* ip = in  + (long long)blockIdx.z * sIn;
    float*       op = out + (long long)blockIdx.z * sOut;
    const int c0 = blockIdx.x * 32, r0 = blockIdx.y * 32;
    const int x = threadIdx.x & 31, y = threadIdx.x >> 5;

    #pragma unroll
    for (int i = 0; i < 4; i++)
        tile[y + 8 * i][x] = ip[(long long)(r0 + y + 8 * i) * Cd + c0 + x];
    __syncthreads();
    #pragma unroll
    for (int i = 0; i < 4; i++)
        op[(long long)(c0 + y + 8 * i) * R + r0 + x] = tile[x][y + 8 * i];
}

// ---------------- tf32 mma.sync GEMM, 128x128 tile, 64x64 warp tile ----------
// 128 threads (2x2 warps), 2 CTAs/SM. 2-stage cp.async + frag pipeline.
// C[m,n] = alpha * sum_k A[m*lda+k] * B[k*ldb+n] (+ bias[m]) (+ res[m*ldc+n])
// All operands MUST be tf32-pre-rounded. ROUND: tf32-round outputs.
#define BM 128
#define BN 128
#define BK 32
#define ASTR 36     // 36 mod 32 = 4 -> A frag banks = 4g + t (conflict-free)
#define BSTR 136    // 136 mod 32 = 8 -> B frag banks = 8t + g (conflict-free)
#define ASZ (BM * ASTR)     // 4608 floats
#define BSZ (BK * BSTR)     // 4352 floats
#define GEMM_SMEM ((2 * ASZ + 2 * BSZ) * 4)   // 71680 B

__device__ __forceinline__ void cp16(uint32_t dst, const float* src) {
    asm volatile("cp.async.ca.shared.global [%0], [%1], 16;" :: "r"(dst), "l"(src));
}

__device__ __forceinline__ void mma8(float* c, const uint32_t* a, const uint32_t* b) {
    asm volatile(
        "mma.sync.aligned.m16n8k8.row.col.f32.tf32.tf32.f32 "
        "{%0,%1,%2,%3}, {%4,%5,%6,%7}, {%8,%9}, {%0,%1,%2,%3};"
        : "+f"(c[0]), "+f"(c[1]), "+f"(c[2]), "+f"(c[3])
        : "r"(a[0]), "r"(a[1]), "r"(a[2]), "r"(a[3]), "r"(b[0]), "r"(b[1]));
}

template<bool ROUND>
__global__ void __launch_bounds__(128, 2)
gemm_tf32_nn(const float* __restrict__ A, long long sA,
             const float* __restrict__ B, long long sB,
             const float* __restrict__ bias,
             const float* __restrict__ res, long long sRes,
             float* __restrict__ C, long long sC,
             int K, int lda, int ldb, int ldc, float alpha)
{
    extern __shared__ float smf[];
    float* As = smf;                 // 2 buffers of [128][36]
    float* Bs = smf + 2 * ASZ;       // 2 buffers of [32][136]

    const int z = blockIdx.z;
    A += (long long)z * sA;
    B += (long long)z * sB;
    C += (long long)z * sC;
    const float* R = res ? res + (long long)z * sRes : nullptr;

    const int bm = blockIdx.y * BM;
    const int bn = blockIdx.x * BN;
    const int tid  = threadIdx.x;         // 0..127
    const int warp = tid >> 5, lane = tid & 31;
    const int wm = warp >> 1, wn = warp & 1;   // 2x2 warp grid, 64x64 each
    const int g  = lane >> 2, t  = lane & 3;

    const int a_kq = tid & 7,  a_m = tid >> 3;   // A fill: 8 k-quads x 16 rows
    const int b_nq = tid & 31, b_k = tid >> 5;   // B fill: 32 n-quads x 4 k rows

    const uint32_t as_u = (uint32_t)__cvta_generic_to_shared(As);
    const uint32_t bs_u = (uint32_t)__cvta_generic_to_shared(Bs);

    float acc[4][8][4];
    #pragma unroll
    for (int i = 0; i < 4; i++)
        #pragma unroll
        for (int j = 0; j < 8; j++)
            #pragma unroll
            for (int q = 0; q < 4; q++) acc[i][j][q] = 0.f;

    auto fill = [&](int buf, int k0) {
        const uint32_t ab = as_u + (uint32_t)(buf * ASZ * 4);
        const uint32_t bb = bs_u + (uint32_t)(buf * BSZ * 4);
        #pragma unroll
        for (int mi = 0; mi < 8; mi++) {
            const int row = a_m + 16 * mi;
            cp16(ab + (uint32_t)((row * ASTR + a_kq * 4) * 4),
                 A + (long long)(bm + row) * lda + k0 + a_kq * 4);
        }
        #pragma unroll
        for (int ki = 0; ki < 8; ki++) {
            const int k = b_k + 4 * ki;
            cp16(bb + (uint32_t)((k * BSTR + b_nq * 4) * 4),
                 B + (long long)(k0 + k) * ldb + bn + b_nq * 4);
        }
        asm volatile("cp.async.commit_group;" ::: "memory");
    };

    const int nk = K / BK;
    fill(0, 0);
    int buf = 0;

    for (int ks = 0; ks < nk; ks++) {
        if (ks + 1 < nk) {
            fill(buf ^ 1, (ks + 1) * BK);
            asm volatile("cp.async.wait_group 1;" ::: "memory");
        } else {
            asm volatile("cp.async.wait_group 0;" ::: "memory");
        }
        __syncthreads();

        const uint32_t* Ab = (const uint32_t*)(As + buf * ASZ);
        const uint32_t* Bb = (const uint32_t*)(Bs + buf * BSZ);

        // register fragment pipeline: 2-deep (current / next k8)
        uint32_t af[2][4][4], bf[2][8][2];

        #pragma unroll
        for (int nt = 0; nt < 8; nt++) {
            const int col = wn * 64 + nt * 8 + g;
            bf[0][nt][0] = Bb[t * BSTR + col];
            bf[0][nt][1] = Bb[(t + 4) * BSTR + col];
        }
        #pragma unroll
        for (int mt = 0; mt < 4; mt++) {
            const int row = wm * 64 + mt * 16 + g;
            af[0][mt][0] = Ab[row * ASTR + t];
            af[0][mt][1] = Ab[(row + 8) * ASTR + t];
            af[0][mt][2] = Ab[row * ASTR + t + 4];
            af[0][mt][3] = Ab[(row + 8) * ASTR + t + 4];
        }

        #pragma unroll
        for (int k8 = 0; k8 < 4; k8++) {
            const int c = k8 & 1, nx = c ^ 1;
            if (k8 < 3) {
                const int kk = (k8 + 1) * 8;
                #pragma unroll
                for (int nt = 0; nt < 8; nt++) {
                    const int col = wn * 64 + nt * 8 + g;
                    bf[nx][nt][0] = Bb[(kk + t) * BSTR + col];
                    bf[nx][nt][1] = Bb[(kk + t + 4) * BSTR + col];
                }
                #pragma unroll
                for (int mt = 0; mt < 4; mt++) {
                    const int row = wm * 64 + mt * 16 + g;
                    af[nx][mt][0] = Ab[row * ASTR + kk + t];
                    af[nx][mt][1] = Ab[(row + 8) * ASTR + kk + t];
                    af[nx][mt][2] = Ab[row * ASTR + kk + t + 4];
                    af[nx][mt][3] = Ab[(row + 8) * ASTR + kk + t + 4];
                }
            }
            #pragma unroll
            for (int mt = 0; mt < 4; mt++)
                #pragma unroll
                for (int nt = 0; nt < 8; nt++)
                    mma8(acc[mt][nt], af[c][mt], bf[c][nt]);
        }
        __syncthreads();
        buf ^= 1;
    }

    // epilogue: c0:(g,2t) c1:(g,2t+1) c2:(g+8,2t) c3:(g+8,2t+1)
    #pragma unroll
    for (int mt = 0; mt < 4; mt++) {
        const int r0 = bm + wm * 64 + mt * 16 + g;
        const float bi0 = bias ? bias[r0]     : 0.f;
        const float bi1 = bias ? bias[r0 + 8] : 0.f;
        #pragma unroll
        for (int nt = 0; nt < 8; nt++) {
            const int c0 = bn + wn * 64 + nt * 8 + 2 * t;
            float2 v0, v1;
            v0.x = acc[mt][nt][0] * alpha + bi0;
            v0.y = acc[mt][nt][1] * alpha + bi0;
            v1.x = acc[mt][nt][2] * alpha + bi1;
            v1.y = acc[mt][nt][3] * alpha + bi1;
            if (R) {
                const float2 r0v = *(const float2*)&R[(long long)r0 * ldc + c0];
                const float2 r1v = *(const float2*)&R[(long long)(r0 + 8) * ldc + c0];
                v0.x += r0v.x; v0.y += r0v.y;
                v1.x += r1v.x; v1.y += r1v.y;
            }
            if (ROUND) {
                v0.x = f2tf32(v0.x); v0.y = f2tf32(v0.y);
                v1.x = f2tf32(v1.x); v1.y = f2tf32(v1.y);
            }
            *(float2*)&C[(long long)r0 * ldc + c0]       = v0;
            *(float2*)&C[(long long)(r0 + 8) * ldc + c0] = v1;
        }
    }
}

// ---------------- row softmax (writes tf32-rounded P) ------------------------
__global__ void __launch_bounds__(256)
softmax_kernel(float* __restrict__ sm)
{
    float* row = sm + (long long)blockIdx.x * LL;
    const int tid = threadIdx.x;
    const int warp = tid >> 5, lane = tid & 31;

    float v[8];
    float mx = -1e30f;
    #pragma unroll
    for (int i = 0; i < 8; i++) {
        v[i] = row[tid + 256 * i];
        mx = fmaxf(mx, v[i]);
    }
    __shared__ float red[32];
    __shared__ float bcast;
    #pragma unroll
    for (int o = 16; o; o >>= 1) mx = fmaxf(mx, __shfl_xor_sync(0xffffffffu, mx, o));
    if (!lane) red[warp] = mx;
    __syncthreads();
    if (tid < 32) {
        float m2 = (tid < 8) ? red[tid] : -1e30f;
        #pragma unroll
        for (int o = 4; o; o >>= 1) m2 = fmaxf(m2, __shfl_xor_sync(0xffffffffu, m2, o));
        if (!tid) bcast = m2;
    }
    __syncthreads();
    mx = bcast;

    float s = 0.f;
    #pragma unroll
    for (int i = 0; i < 8; i++) {
        v[i] = expf(v[i] - mx);
        s += v[i];
    }
    #pragma unroll
    for (int o = 16; o; o >>= 1) s += __shfl_xor_sync(0xffffffffu, s, o);
    if (!lane) red[warp] = s;
    __syncthreads();
    if (tid < 32) {
        float s2 = (tid < 8) ? red[tid] : 0.f;
        #pragma unroll
        for (int o = 4; o; o >>= 1) s2 += __shfl_xor_sync(0xffffffffu, s2, o);
        if (!tid) bcast = s2;
    }
    __syncthreads();
    const float inv = 1.f / bcast;
    #pragma unroll
    for (int i = 0; i < 8; i++) row[tid + 256 * i] = f2tf32(v[i] * inv);
}

// ---------------- launch ------------------------------------------------------
extern "C" void kernel_launch(void* const* d_in, const int* in_sizes, int n_in,
                              void* d_out, int out_size)
{
    const float* x  = (const float*)d_in[0];
    const float* gw = (const float*)d_in[1];
    const float* gb = (const float*)d_in[2];
    const float* wq = (const float*)d_in[3];
    const float* bq = (const float*)d_in[4];
    const float* wk = (const float*)d_in[5];
    const float* bk = (const float*)d_in[6];
    const float* wv = (const float*)d_in[7];
    const float* bv = (const float*)d_in[8];
    const float* wo = (const float*)d_in[9];
    const float* bo = (const float*)d_in[10];
    float* out = (float*)d_out;

    float *h, *ht, *qkv, *h2, *s, *w, *bc;
    cudaGetSymbolAddress((void**)&h,   g_h);
    cudaGetSymbolAddress((void**)&ht,  g_ht);
    cudaGetSymbolAddress((void**)&qkv, g_qkv);
    cudaGetSymbolAddress((void**)&h2,  g_h2);
    cudaGetSymbolAddress((void**)&s,   g_s);
    cudaGetSymbolAddress((void**)&w,   g_w);
    cudaGetSymbolAddress((void**)&bc,  g_bc);

    float* wqkv = w;                    // wq|wk|wv stacked = rows 0..1535
    float* wot  = w + 3 * CC * CC;

    cudaFuncSetAttribute(gemm_tf32_nn<true>,
                         cudaFuncAttributeMaxDynamicSharedMemorySize, GEMM_SMEM);
    cudaFuncSetAttribute(gemm_tf32_nn<false>,
                         cudaFuncAttributeMaxDynamicSharedMemorySize, GEMM_SMEM);

    const float scale = 0.044194173824159216f;   // 512^-0.5
    dim3 blk(128);

    // 0) tf32 copies of all weights + bias concat
    cvt4_kernel<<<1024, 256>>>((const float4*)wq, (const float4*)wk,
                               (const float4*)wv, (const float4*)wo, (float4*)w);
    bcat_kernel<<<6, 256>>>(bq, bk, bv, bc);

    // 1) GroupNorm -> h [C][L] (tf32)
    gn_kernel<<<BB * NG, 256>>>(x, gw, gb, h);

    // 2) fused QKV = [wq|wk|wv] @ H_b + bcat  (M=3C=1536, N=L, K=C)
    dim3 gQKV(LL / BN, 3 * CC / BM, BB);   // (16,12,8) = 1536 CTAs
    gemm_tf32_nn<true><<<gQKV, blk, GEMM_SMEM>>>(
        wqkv, 0LL, h, CL, bc, nullptr, 0LL, qkv, C3L, CC, CC, LL, LL, 1.f);

    // 3) qT [L][C] into g_ht  (q = qkv rows 0..511)
    transpose_kernel<<<dim3(LL / 32, CC / 32, BB), 256>>>(qkv, C3L, ht, CL, CC, LL);

    // 4) S = scale * qT @ k  (M=L, N=L, K=C; k = qkv+CL; fp32 scores out)
    dim3 gS(LL / BN, LL / BM, BB);         // (16,16,8)
    gemm_tf32_nn<false><<<gS, blk, GEMM_SMEM>>>(
        ht, CL, qkv + CL, C3L, nullptr, nullptr, 0LL, s, LL2, CC, CC, LL, LL, scale);

    // 5) row softmax (tf32-rounded P)
    softmax_kernel<<<BB * LL, 256>>>(s);

    // 6) vT [L][C] into g_h (h dead after QKV; v = qkv+2CL)
    transpose_kernel<<<dim3(LL / 32, CC / 32, BB), 256>>>(qkv + 2 * CL, C3L, h, CL, CC, LL);

    // 7) h2T = P @ vT  (M=L, N=C, K=L; lda=LL, ldb=CC)
    dim3 gA(CC / BN, LL / BM, BB);         // (4,16,8)
    gemm_tf32_nn<true><<<gA, blk, GEMM_SMEM>>>(
        s, LL2, h, CL, nullptr, nullptr, 0LL, h2, CL, LL, LL, CC, CC, 1.f);

    // 8) h2 [C][L] into g_ht (ht dead after scores)
    transpose_kernel<<<dim3(CC / 32, LL / 32, BB), 256>>>(h2, CL, ht, CL, LL, CC);

    // 9) out = x + wo @ h2 + bo  (M=C, N=L, K=C; fp32 out)
    dim3 gO(LL / BN, CC / BM, BB);         // (16,4,8)
    gemm_tf32_nn<false><<<gO, blk, GEMM_SMEM>>>(
        wot, 0LL, ht, CL, bo, x, CL, out, CL, CC, CC, LL, LL, 1.f);
}

// round 14
// speedup vs baseline: 1.2992x; 1.0355x over previous
#include <cuda_runtime.h>
#include <math.h>
#include <stdint.h>

// Problem dims (fixed by the reference setup)
#define BB 8
#define CC 512
#define LL 2048
#define NG 32
#define CPG 16

static const long long CL  = (long long)CC * LL;      // 1,048,576
static const long long C3L = 3LL * CC * LL;           // 3,145,728
static const long long LL2 = (long long)LL * LL;      // 4,194,304

// ---------------- scratch (device globals; no cudaMalloc allowed) ----------
__device__ float g_h  [BB * CC * LL];              // gn out h [C][L]
__device__ float g_qkv[BB * 3 * CC * LL];          // fused q/k/v [3C][L] per batch
__device__ float g_h2 [BB * CC * LL];              // h2T [L][C]
__device__ float g_s  [(long long)BB * LL * LL];   // scores -> softmax P [L][L]
__device__ float g_w  [4 * CC * CC];               // tf32 wq,wk,wv,wo (contiguous)
__device__ float g_bc [3 * CC];                    // concat bq,bk,bv

__device__ __forceinline__ float f2tf32(float f) {
    uint32_t u;
    asm("cvt.rna.tf32.f32 %0, %1;" : "=r"(u) : "f"(f));
    return __uint_as_float(u);
}

// ---------------- weight tf32 conversion (one launch) ------------------------
__global__ void __launch_bounds__(256)
cvt4_kernel(const float4* __restrict__ a, const float4* __restrict__ b,
            const float4* __restrict__ c, const float4* __restrict__ d,
            float4* __restrict__ out)
{
    int i = blockIdx.x * 256 + threadIdx.x;       // 0 .. 262143
    int seg = i >> 16, off = i & 65535;
    const float4* src = (seg == 0) ? a : (seg == 1) ? b : (seg == 2) ? c : d;
    float4 v = src[off];
    v.x = f2tf32(v.x); v.y = f2tf32(v.y);
    v.z = f2tf32(v.z); v.w = f2tf32(v.w);
    out[i] = v;
}

// ---------------- bias concat (bq|bk|bv) --------------------------------------
__global__ void __launch_bounds__(256)
bcat_kernel(const float* __restrict__ bq, const float* __restrict__ bk,
            const float* __restrict__ bv, float* __restrict__ out)
{
    int i = blockIdx.x * 256 + threadIdx.x;       // 0..1535
    if (i < CC)            out[i] = bq[i];
    else if (i < 2 * CC)   out[i] = bk[i - CC];
    else if (i < 3 * CC)   out[i] = bv[i - 2 * CC];
}

// ---------------- GroupNorm (writes tf32-rounded output) ---------------------
__global__ void __launch_bounds__(256)
gn_kernel(const float* __restrict__ x, const float* __restrict__ gw,
          const float* __restrict__ gb, float* __restrict__ h)
{
    const int blk   = blockIdx.x;
    const int batch = blk >> 5;
    const int g     = blk & 31;
    const long long base = (long long)batch * CC * LL + (long long)g * CPG * LL;
    const float* xp = x + base;
    float*       hp = h + base;
    const int tid = threadIdx.x;
    const int NEL = CPG * LL;   // 32768

    float s = 0.f, ss = 0.f;
    for (int i = tid; i < NEL; i += 256) {
        float v = xp[i];
        s += v; ss += v * v;
    }
    __shared__ float rs[32], rss[32];
    #pragma unroll
    for (int o = 16; o; o >>= 1) {
        s  += __shfl_xor_sync(0xffffffffu, s,  o);
        ss += __shfl_xor_sync(0xffffffffu, ss, o);
    }
    const int warp = tid >> 5, lane = tid & 31;
    if (!lane) { rs[warp] = s; rss[warp] = ss; }
    __syncthreads();
    if (tid < 32) {
        float s2  = (tid < 8) ? rs[tid]  : 0.f;
        float ss2 = (tid < 8) ? rss[tid] : 0.f;
        #pragma unroll
        for (int o = 4; o; o >>= 1) {
            s2  += __shfl_xor_sync(0xffffffffu, s2,  o);
            ss2 += __shfl_xor_sync(0xffffffffu, ss2, o);
        }
        if (!tid) {
            float mean = s2 / (float)NEL;
            float var  = ss2 / (float)NEL - mean * mean;
            rs[0]  = mean;
            rss[0] = rsqrtf(var + 1e-6f);
        }
    }
    __syncthreads();
    const float mean = rs[0], inv = rss[0];
    for (int i = tid; i < NEL; i += 256) {
        int c = g * CPG + (i >> 11);
        hp[i] = f2tf32((xp[i] - mean) * inv * gw[c] + gb[c]);
    }
}

// ---------------- tf32 mma.sync GEMM, 128x128 tile, 64x64 warp tile ----------
// 128 threads (2x2 warps), 2 CTAs/SM. 2-stage cp.async + frag pipeline.
// C[m,n] = alpha * sum_k opA[m][k] * opB[k][n] (+ bias[m]) (+ res[m*ldc+n])
//   TA=false: A global is [M][K] row-major (lda = K-stride of a row)
//   TA=true : A global is [K][M] row-major (lda = M-stride of a row) - read as A^T
//   TB=false: B global is [K][N] row-major
//   TB=true : B global is [N][K] row-major - read as B^T
// All operands MUST be tf32-pre-rounded. ROUND: tf32-round outputs.
#define BM 128
#define BN 128
#define BK 32
// smem layouts (all mod-32 = 4 or 8 -> conflict-free frag loads, see notes):
//   A NN: As[m][k],  stride 36  (frag banks 4g+t)
//   A TN: As[k][m],  stride 132 (frag banks 4t+g)
//   B NN: Bs[k][n],  stride 136 (frag banks 8t+g)
//   B TB: Bs[n][k],  stride 36  (frag banks 4g+t)
#define ASZ_MAX 4608     // max(128*36, 32*132)
#define BSZ_MAX 4608     // max(32*136, 128*36)
#define GEMM_SMEM ((2 * ASZ_MAX + 2 * BSZ_MAX) * 4)   // 73728 B

__device__ __forceinline__ void cp16(uint32_t dst, const float* src) {
    asm volatile("cp.async.ca.shared.global [%0], [%1], 16;" :: "r"(dst), "l"(src));
}

__device__ __forceinline__ void mma8(float* c, const uint32_t* a, const uint32_t* b) {
    asm volatile(
        "mma.sync.aligned.m16n8k8.row.col.f32.tf32.tf32.f32 "
        "{%0,%1,%2,%3}, {%4,%5,%6,%7}, {%8,%9}, {%0,%1,%2,%3};"
        : "+f"(c[0]), "+f"(c[1]), "+f"(c[2]), "+f"(c[3])
        : "r"(a[0]), "r"(a[1]), "r"(a[2]), "r"(a[3]), "r"(b[0]), "r"(b[1]));
}

template<bool TA, bool TB, bool ROUND>
__global__ void __launch_bounds__(128, 2)
gemm_tf32(const float* __restrict__ A, long long sA,
          const float* __restrict__ B, long long sB,
          const float* __restrict__ bias,
          const float* __restrict__ res, long long sRes,
          float* __restrict__ C, long long sC,
          int K, int lda, int ldb, int ldc, float alpha)
{
    extern __shared__ float smf[];
    float* As = smf;                       // 2 buffers of ASZ_MAX
    float* Bs = smf + 2 * ASZ_MAX;         // 2 buffers of BSZ_MAX

    const int z = blockIdx.z;
    A += (long long)z * sA;
    B += (long long)z * sB;
    C += (long long)z * sC;
    const float* R = res ? res + (long long)z * sRes : nullptr;

    const int bm = blockIdx.y * BM;
    const int bn = blockIdx.x * BN;
    const int tid  = threadIdx.x;          // 0..127
    const int warp = tid >> 5, lane = tid & 31;
    const int wm = warp >> 1, wn = warp & 1;   // 2x2 warp grid, 64x64 each
    const int g  = lane >> 2, t  = lane & 3;

    const uint32_t as_u = (uint32_t)__cvta_generic_to_shared(As);
    const uint32_t bs_u = (uint32_t)__cvta_generic_to_shared(Bs);

    float acc[4][8][4];
    #pragma unroll
    for (int i = 0; i < 4; i++)
        #pragma unroll
        for (int j = 0; j < 8; j++)
            #pragma unroll
            for (int q = 0; q < 4; q++) acc[i][j][q] = 0.f;

    auto fill = [&](int buf, int k0) {
        const uint32_t ab = as_u + (uint32_t)(buf * ASZ_MAX * 4);
        const uint32_t bb = bs_u + (uint32_t)(buf * BSZ_MAX * 4);
        if (!TA) {
            // A[m][k]: 8 rows/iter x (tid>>3), 8 k-quads
            const int kq = tid & 7, m0 = tid >> 3;
            #pragma unroll
            for (int i = 0; i < 8; i++) {
                const int row = m0 + 16 * i;
                cp16(ab + (uint32_t)((row * 36 + kq * 4) * 4),
                     A + (long long)(bm + row) * lda + k0 + kq * 4);
            }
        } else {
            // A[k][m]: 4 k-rows/iter, 32 m-quads
            const int mq = tid & 31, kk0 = tid >> 5;
            #pragma unroll
            for (int i = 0; i < 8; i++) {
                const int k = kk0 + 4 * i;
                cp16(ab + (uint32_t)((k * 132 + mq * 4) * 4),
                     A + (long long)(k0 + k) * lda + bm + mq * 4);
            }
        }
        if (!TB) {
            // B[k][n]: 4 k-rows/iter, 32 n-quads
            const int nq = tid & 31, kk0 = tid >> 5;
            #pragma unroll
            for (int i = 0; i < 8; i++) {
                const int k = kk0 + 4 * i;
                cp16(bb + (uint32_t)((k * 136 + nq * 4) * 4),
                     B + (long long)(k0 + k) * ldb + bn + nq * 4);
            }
        } else {
            // B[n][k]: 16 n-rows/iter, 8 k-quads
            const int kq = tid & 7, n0 = tid >> 3;
            #pragma unroll
            for (int i = 0; i < 8; i++) {
                const int n = n0 + 16 * i;
                cp16(bb + (uint32_t)((n * 36 + kq * 4) * 4),
                     B + (long long)(bn + n) * ldb + k0 + kq * 4);
            }
        }
        asm volatile("cp.async.commit_group;" ::: "memory");
    };

    const int nk = K / BK;
    fill(0, 0);
    int buf = 0;

    for (int ks = 0; ks < nk; ks++) {
        if (ks + 1 < nk) {
            fill(buf ^ 1, (ks + 1) * BK);
            asm volatile("cp.async.wait_group 1;" ::: "memory");
        } else {
            asm volatile("cp.async.wait_group 0;" ::: "memory");
        }
        __syncthreads();

        const uint32_t* Ab = (const uint32_t*)(As + buf * ASZ_MAX);
        const uint32_t* Bb = (const uint32_t*)(Bs + buf * BSZ_MAX);

        auto ldA = [&](uint32_t* af, int kk, int mt) {
            const int row = wm * 64 + mt * 16 + g;
            if (!TA) {
                af[0] = Ab[row * 36 + kk + t];
                af[1] = Ab[(row + 8) * 36 + kk + t];
                af[2] = Ab[row * 36 + kk + t + 4];
                af[3] = Ab[(row + 8) * 36 + kk + t + 4];
            } else {
                af[0] = Ab[(kk + t) * 132 + row];
                af[1] = Ab[(kk + t) * 132 + row + 8];
                af[2] = Ab[(kk + t + 4) * 132 + row];
                af[3] = Ab[(kk + t + 4) * 132 + row + 8];
            }
        };
        auto ldB = [&](uint32_t* bf, int kk, int nt) {
            const int col = wn * 64 + nt * 8 + g;
            if (!TB) {
                bf[0] = Bb[(kk + t) * 136 + col];
                bf[1] = Bb[(kk + t + 4) * 136 + col];
            } else {
                bf[0] = Bb[col * 36 + kk + t];
                bf[1] = Bb[col * 36 + kk + t + 4];
            }
        };

        // register fragment pipeline: 2-deep (current / next k8)
        uint32_t af[2][4][4], bf[2][8][2];
        #pragma unroll
        for (int nt = 0; nt < 8; nt++) ldB(bf[0][nt], 0, nt);
        #pragma unroll
        for (int mt = 0; mt < 4; mt++) ldA(af[0][mt], 0, mt);

        #pragma unroll
        for (int k8 = 0; k8 < 4; k8++) {
            const int c = k8 & 1, nx = c ^ 1;
            if (k8 < 3) {
                const int kk = (k8 + 1) * 8;
                #pragma unroll
                for (int nt = 0; nt < 8; nt++) ldB(bf[nx][nt], kk, nt);
                #pragma unroll
                for (int mt = 0; mt < 4; mt++) ldA(af[nx][mt], kk, mt);
            }
            #pragma unroll
            for (int mt = 0; mt < 4; mt++)
                #pragma unroll
                for (int nt = 0; nt < 8; nt++)
                    mma8(acc[mt][nt], af[c][mt], bf[c][nt]);
        }
        __syncthreads();
        buf ^= 1;
    }

    // epilogue: c0:(g,2t) c1:(g,2t+1) c2:(g+8,2t) c3:(g+8,2t+1)
    #pragma unroll
    for (int mt = 0; mt < 4; mt++) {
        const int r0 = bm + wm * 64 + mt * 16 + g;
        const float bi0 = bias ? bias[r0]     : 0.f;
        const float bi1 = bias ? bias[r0 + 8] : 0.f;
        #pragma unroll
        for (int nt = 0; nt < 8; nt++) {
            const int c0 = bn + wn * 64 + nt * 8 + 2 * t;
            float2 v0, v1;
            v0.x = acc[mt][nt][0] * alpha + bi0;
            v0.y = acc[mt][nt][1] * alpha + bi0;
            v1.x = acc[mt][nt][2] * alpha + bi1;
            v1.y = acc[mt][nt][3] * alpha + bi1;
            if (R) {
                const float2 r0v = *(const float2*)&R[(long long)r0 * ldc + c0];
                const float2 r1v = *(const float2*)&R[(long long)(r0 + 8) * ldc + c0];
                v0.x += r0v.x; v0.y += r0v.y;
                v1.x += r1v.x; v1.y += r1v.y;
            }
            if (ROUND) {
                v0.x = f2tf32(v0.x); v0.y = f2tf32(v0.y);
                v1.x = f2tf32(v1.x); v1.y = f2tf32(v1.y);
            }
            *(float2*)&C[(long long)r0 * ldc + c0]       = v0;
            *(float2*)&C[(long long)(r0 + 8) * ldc + c0] = v1;
        }
    }
}

// ---------------- row softmax (writes tf32-rounded P) ------------------------
__global__ void __launch_bounds__(256)
softmax_kernel(float* __restrict__ sm)
{
    float* row = sm + (long long)blockIdx.x * LL;
    const int tid = threadIdx.x;
    const int warp = tid >> 5, lane = tid & 31;

    float v[8];
    float mx = -1e30f;
    #pragma unroll
    for (int i = 0; i < 8; i++) {
        v[i] = row[tid + 256 * i];
        mx = fmaxf(mx, v[i]);
    }
    __shared__ float red[32];
    __shared__ float bcast;
    #pragma unroll
    for (int o = 16; o; o >>= 1) mx = fmaxf(mx, __shfl_xor_sync(0xffffffffu, mx, o));
    if (!lane) red[warp] = mx;
    __syncthreads();
    if (tid < 32) {
        float m2 = (tid < 8) ? red[tid] : -1e30f;
        #pragma unroll
        for (int o = 4; o; o >>= 1) m2 = fmaxf(m2, __shfl_xor_sync(0xffffffffu, m2, o));
        if (!tid) bcast = m2;
    }
    __syncthreads();
    mx = bcast;

    float s = 0.f;
    #pragma unroll
    for (int i = 0; i < 8; i++) {
        v[i] = expf(v[i] - mx);
        s += v[i];
    }
    #pragma unroll
    for (int o = 16; o; o >>= 1) s += __shfl_xor_sync(0xffffffffu, s, o);
    if (!lane) red[warp] = s;
    __syncthreads();
    if (tid < 32) {
        float s2 = (tid < 8) ? red[tid] : 0.f;
        #pragma unroll
        for (int o = 4; o; o >>= 1) s2 += __shfl_xor_sync(0xffffffffu, s2, o);
        if (!tid) bcast = s2;
    }
    __syncthreads();
    const float inv = 1.f / bcast;
    #pragma unroll
    for (int i = 0; i < 8; i++) row[tid + 256 * i] = f2tf32(v[i] * inv);
}

// ---------------- launch ------------------------------------------------------
extern "C" void kernel_launch(void* const* d_in, const int* in_sizes, int n_in,
                              void* d_out, int out_size)
{
    const float* x  = (const float*)d_in[0];
    const float* gw = (const float*)d_in[1];
    const float* gb = (const float*)d_in[2];
    const float* wq = (const float*)d_in[3];
    const float* bq = (const float*)d_in[4];
    const float* wk = (const float*)d_in[5];
    const float* bk = (const float*)d_in[6];
    const float* wv = (const float*)d_in[7];
    const float* bv = (const float*)d_in[8];
    const float* wo = (const float*)d_in[9];
    const float* bo = (const float*)d_in[10];
    float* out = (float*)d_out;

    float *h, *qkv, *h2, *s, *w, *bc;
    cudaGetSymbolAddress((void**)&h,   g_h);
    cudaGetSymbolAddress((void**)&qkv, g_qkv);
    cudaGetSymbolAddress((void**)&h2,  g_h2);
    cudaGetSymbolAddress((void**)&s,   g_s);
    cudaGetSymbolAddress((void**)&w,   g_w);
    cudaGetSymbolAddress((void**)&bc,  g_bc);

    float* wqkv = w;                    // wq|wk|wv stacked = rows 0..1535
    float* wot  = w + 3 * CC * CC;

    cudaFuncSetAttribute(gemm_tf32<false, false, true>,
                         cudaFuncAttributeMaxDynamicSharedMemorySize, GEMM_SMEM);
    cudaFuncSetAttribute(gemm_tf32<true, false, false>,
                         cudaFuncAttributeMaxDynamicSharedMemorySize, GEMM_SMEM);
    cudaFuncSetAttribute(gemm_tf32<false, true, true>,
                         cudaFuncAttributeMaxDynamicSharedMemorySize, GEMM_SMEM);
    cudaFuncSetAttribute(gemm_tf32<false, true, false>,
                         cudaFuncAttributeMaxDynamicSharedMemorySize, GEMM_SMEM);

    const float scale = 0.044194173824159216f;   // 512^-0.5
    dim3 blk(128);

    // 0) tf32 copies of all weights + bias concat
    cvt4_kernel<<<1024, 256>>>((const float4*)wq, (const float4*)wk,
                               (const float4*)wv, (const float4*)wo, (float4*)w);
    bcat_kernel<<<6, 256>>>(bq, bk, bv, bc);

    // 1) GroupNorm -> h [C][L] (tf32)
    gn_kernel<<<BB * NG, 256>>>(x, gw, gb, h);

    // 2) fused QKV = [wq|wk|wv] @ H_b + bcat  (M=3C, N=L, K=C)
    dim3 gQKV(LL / BN, 3 * CC / BM, BB);   // (16,12,8)
    gemm_tf32<false, false, true><<<gQKV, blk, GEMM_SMEM>>>(
        wqkv, 0LL, h, CL, bc, nullptr, 0LL, qkv, C3L, CC, CC, LL, LL, 1.f);

    // 3) S = scale * q^T @ k  (M=L, N=L, K=C; A=q [C][L] read transposed)
    dim3 gS(LL / BN, LL / BM, BB);         // (16,16,8)
    gemm_tf32<true, false, false><<<gS, blk, GEMM_SMEM>>>(
        qkv, C3L, qkv + CL, C3L, nullptr, nullptr, 0LL,
        s, LL2, CC, LL, LL, LL, scale);

    // 4) row softmax (tf32-rounded P)
    softmax_kernel<<<BB * LL, 256>>>(s);

    // 5) h2T = P @ v^T  (M=L, N=C, K=L; B=v [C][L] read transposed; ROUND)
    dim3 gA(CC / BN, LL / BM, BB);         // (4,16,8)
    gemm_tf32<false, true, true><<<gA, blk, GEMM_SMEM>>>(
        s, LL2, qkv + 2 * CL, C3L, nullptr, nullptr, 0LL,
        h2, CL, LL, LL, LL, CC, 1.f);

    // 6) out = x + wo @ h2 + bo  (M=C, N=L, K=C; B=h2T [L][C] read transposed)
    dim3 gO(LL / BN, CC / BM, BB);         // (16,4,8)
    gemm_tf32<false, true, false><<<gO, blk, GEMM_SMEM>>>(
        wot, 0LL, h2, CL, bo, x, CL, out, CL, CC, CC, CC, LL, 1.f);
}

// round 15
// speedup vs baseline: 1.9862x; 1.5288x over previous
#include <cuda_runtime.h>
#include <cuda_bf16.h>
#include <math.h>
#include <stdint.h>

// Problem dims (fixed by the reference setup)
#define BB 8
#define CC 512
#define LL 2048
#define NG 32
#define CPG 16

static const long long CL  = (long long)CC * LL;      // 1,048,576
static const long long LL2 = (long long)LL * LL;      // 4,194,304

// ---------------- scratch (device globals; no cudaMalloc allowed) ----------
__device__ __nv_bfloat16 g_ht[BB * CC * LL];              // hT [L][C]
__device__ __nv_bfloat16 g_qk[BB * 2 * CC * LL];          // qkT [L][2C]
__device__ __nv_bfloat16 g_v [BB * CC * LL];              // v [C][L]
__device__ __nv_bfloat16 g_h2[BB * CC * LL];              // h2T [L][C]
__device__ float         g_s [(long long)BB * LL * LL];   // scores fp32 [L][L]
__device__ __nv_bfloat16 g_p [(long long)BB * LL * LL];   // softmax P bf16 [L][L]
__device__ __nv_bfloat16 g_wh[4 * CC * CC];               // bf16 wq,wk,wv,wo
__device__ float         g_bc[2 * CC];                    // concat bq,bk

// ---------------- weight bf16 conversion (one launch) ------------------------
__global__ void __launch_bounds__(256)
cvtb_kernel(const float4* __restrict__ a, const float4* __restrict__ b,
            const float4* __restrict__ c, const float4* __restrict__ d,
            __nv_bfloat162* __restrict__ out)
{
    int i = blockIdx.x * 256 + threadIdx.x;       // 0 .. 262143
    int seg = i >> 16, off = i & 65535;
    const float4* src = (seg == 0) ? a : (seg == 1) ? b : (seg == 2) ? c : d;
    float4 v = src[off];
    out[2 * i]     = __nv_bfloat162{__float2bfloat16_rn(v.x), __float2bfloat16_rn(v.y)};
    out[2 * i + 1] = __nv_bfloat162{__float2bfloat16_rn(v.z), __float2bfloat16_rn(v.w)};
}

// ---------------- bias concat (bq|bk) -----------------------------------------
__global__ void __launch_bounds__(256)
bcat_kernel(const float* __restrict__ bq, const float* __restrict__ bk,
            float* __restrict__ out)
{
    int i = blockIdx.x * 256 + threadIdx.x;       // 0..1023
    if (i < CC)          out[i] = bq[i];
    else if (i < 2 * CC) out[i] = bk[i - CC];
}

// ---------------- GroupNorm: x [C][L] -> hT [L][C] bf16 ----------------------
__global__ void __launch_bounds__(256)
gn_kernel(const float* __restrict__ x, const float* __restrict__ gw,
          const float* __restrict__ gb, __nv_bfloat16* __restrict__ ht)
{
    const int blk   = blockIdx.x;
    const int batch = blk >> 5;
    const int g     = blk & 31;
    const float* xp = x + (long long)batch * CC * LL + (long long)g * CPG * LL;
    __nv_bfloat16* hb = ht + (long long)batch * CC * LL;
    const int tid = threadIdx.x;
    const int NEL = CPG * LL;   // 32768

    float s = 0.f, ss = 0.f;
    for (int i = tid; i < NEL; i += 256) {
        float v = xp[i];
        s += v; ss += v * v;
    }
    __shared__ float rs[32], rss[32];
    #pragma unroll
    for (int o = 16; o; o >>= 1) {
        s  += __shfl_xor_sync(0xffffffffu, s,  o);
        ss += __shfl_xor_sync(0xffffffffu, ss, o);
    }
    const int warp = tid >> 5, lane = tid & 31;
    if (!lane) { rs[warp] = s; rss[warp] = ss; }
    __syncthreads();
    if (tid < 32) {
        float s2  = (tid < 8) ? rs[tid]  : 0.f;
        float ss2 = (tid < 8) ? rss[tid] : 0.f;
        #pragma unroll
        for (int o = 4; o; o >>= 1) {
            s2  += __shfl_xor_sync(0xffffffffu, s2,  o);
            ss2 += __shfl_xor_sync(0xffffffffu, ss2, o);
        }
        if (!tid) {
            float mean = s2 / (float)NEL;
            float var  = ss2 / (float)NEL - mean * mean;
            rs[0]  = mean;
            rss[0] = rsqrtf(var + 1e-6f);
        }
    }
    __syncthreads();
    const float mean = rs[0], inv = rss[0];

    // staged transpose: tiles of 16 channels x 64 l
    __shared__ __nv_bfloat16 tile[64][17];
    for (int t0 = 0; t0 < LL; t0 += 64) {
        #pragma unroll
        for (int r = 0; r < 4; r++) {
            const int c_local = (tid >> 6) + r * 4;    // 0..15
            const int l_off   = tid & 63;
            const int c = g * CPG + c_local;
            float val = xp[(long long)c_local * LL + t0 + l_off];
            tile[l_off][c_local] =
                __float2bfloat16_rn((val - mean) * inv * gw[c] + gb[c]);
        }
        __syncthreads();
        #pragma unroll
        for (int r = 0; r < 4; r++) {
            const int idx = r * 256 + tid;
            const int l_off = idx >> 4, c_local = idx & 15;
            hb[(long long)(t0 + l_off) * CC + g * CPG + c_local] = tile[l_off][c_local];
        }
        __syncthreads();
    }
}

// ---------------- bf16 mma.sync GEMM, 128x128 tile, 64x64 warp tile ----------
// 128 threads (2x2 warps), 2 CTAs/SM, static smem 40KB, 2-stage cp.async.
// C[m,n] = alpha * sum_k A[m][k] * B[n][k]  (both operands row-major [rows][K])
//          (+ bias: per-M if !BIASN, per-N if BIASN) (+ res[m*ldc+n], fp32)
#define BM 128
#define BN 128
#define BK 32
#define TSTR 40      // smem row stride in bf16 (20 u32; 20 mod 32 = 20 -> 20g+t distinct)
#define TSZ (128 * TSTR)   // 5120 bf16 per tile buffer

__device__ __forceinline__ void cp16(uint32_t dst, const void* src) {
    asm volatile("cp.async.ca.shared.global [%0], [%1], 16;" :: "r"(dst), "l"(src));
}

__device__ __forceinline__ void mma16(float* c, const uint32_t* a, const uint32_t* b) {
    asm volatile(
        "mma.sync.aligned.m16n8k16.row.col.f32.bf16.bf16.f32 "
        "{%0,%1,%2,%3}, {%4,%5,%6,%7}, {%8,%9}, {%0,%1,%2,%3};"
        : "+f"(c[0]), "+f"(c[1]), "+f"(c[2]), "+f"(c[3])
        : "r"(a[0]), "r"(a[1]), "r"(a[2]), "r"(a[3]), "r"(b[0]), "r"(b[1]));
}

__device__ __forceinline__ void store_pair(float* C, long long o, float a, float b) {
    *(float2*)&C[o] = make_float2(a, b);
}
__device__ __forceinline__ void store_pair(__nv_bfloat16* C, long long o, float a, float b) {
    *(__nv_bfloat162*)&C[o] =
        __nv_bfloat162{__float2bfloat16_rn(a), __float2bfloat16_rn(b)};
}

template<bool BIASN, typename TO>
__global__ void __launch_bounds__(128, 2)
gemm_bf16(const __nv_bfloat16* __restrict__ A, long long sA, int lda,
          const __nv_bfloat16* __restrict__ B, long long sB, int ldb,
          const float* __restrict__ bias,
          const float* __restrict__ res, long long sRes,
          TO* __restrict__ C, long long sC, int ldc,
          int K, float alpha)
{
    __shared__ __nv_bfloat16 As[2][TSZ];
    __shared__ __nv_bfloat16 Bs[2][TSZ];

    const int z = blockIdx.z;
    A += (long long)z * sA;
    B += (long long)z * sB;
    C += (long long)z * sC;
    const float* R = res ? res + (long long)z * sRes : nullptr;

    const int bm = blockIdx.y * BM;
    const int bn = blockIdx.x * BN;
    const int tid  = threadIdx.x;          // 0..127
    const int warp = tid >> 5, lane = tid & 31;
    const int wm = warp >> 1, wn = warp & 1;   // 2x2 warp grid, 64x64 each
    const int g  = lane >> 2, t  = lane & 3;

    const uint32_t as_u = (uint32_t)__cvta_generic_to_shared(&As[0][0]);
    const uint32_t bs_u = (uint32_t)__cvta_generic_to_shared(&Bs[0][0]);

    float acc[4][8][4];
    #pragma unroll
    for (int i = 0; i < 4; i++)
        #pragma unroll
        for (int j = 0; j < 8; j++)
            #pragma unroll
            for (int q = 0; q < 4; q++) acc[i][j][q] = 0.f;

    // fill: both tiles are [128 rows][32 k] bf16, 16B chunks of 8 bf16
    const int kq = tid & 3, r0f = tid >> 2;     // 4 k-quads, 32 rows per pass
    auto fill = [&](int buf, int k0) {
        const uint32_t ab = as_u + (uint32_t)(buf * TSZ * 2);
        const uint32_t bb = bs_u + (uint32_t)(buf * TSZ * 2);
        #pragma unroll
        for (int i = 0; i < 4; i++) {
            const int row = r0f + 32 * i;
            cp16(ab + (uint32_t)(row * (TSTR * 2) + kq * 16),
                 A + (long long)(bm + row) * lda + k0 + kq * 8);
        }
        #pragma unroll
        for (int i = 0; i < 4; i++) {
            const int row = r0f + 32 * i;
            cp16(bb + (uint32_t)(row * (TSTR * 2) + kq * 16),
                 B + (long long)(bn + row) * ldb + k0 + kq * 8);
        }
        asm volatile("cp.async.commit_group;" ::: "memory");
    };

    const int nk = K / BK;
    fill(0, 0);
    int buf = 0;

    for (int ks = 0; ks < nk; ks++) {
        if (ks + 1 < nk) {
            fill(buf ^ 1, (ks + 1) * BK);
            asm volatile("cp.async.wait_group 1;" ::: "memory");
        } else {
            asm volatile("cp.async.wait_group 0;" ::: "memory");
        }
        __syncthreads();

        const uint32_t* Ab = (const uint32_t*)&As[buf][0];
        const uint32_t* Bb = (const uint32_t*)&Bs[buf][0];

        // frag loads: u32 index = row*20 + kh*8 + t (pairs along k)
        auto ldA = [&](uint32_t* af, int kh, int mt) {
            const int o = (wm * 64 + mt * 16 + g) * 20 + kh * 8 + t;
            af[0] = Ab[o];       af[1] = Ab[o + 160];
            af[2] = Ab[o + 4];   af[3] = Ab[o + 164];
        };
        auto ldB = [&](uint32_t* bfr, int kh, int nt) {
            const int o = (wn * 64 + nt * 8 + g) * 20 + kh * 8 + t;
            bfr[0] = Bb[o];      bfr[1] = Bb[o + 4];
        };

        uint32_t af[2][4][4], bfr[2][8][2];
        #pragma unroll
        for (int nt = 0; nt < 8; nt++) ldB(bfr[0][nt], 0, nt);
        #pragma unroll
        for (int mt = 0; mt < 4; mt++) ldA(af[0][mt], 0, mt);

        #pragma unroll
        for (int kh = 0; kh < 2; kh++) {
            const int c = kh & 1, nx = c ^ 1;
            if (kh == 0) {
                #pragma unroll
                for (int nt = 0; nt < 8; nt++) ldB(bfr[nx][nt], 1, nt);
                #pragma unroll
                for (int mt = 0; mt < 4; mt++) ldA(af[nx][mt], 1, mt);
            }
            #pragma unroll
            for (int mt = 0; mt < 4; mt++)
                #pragma unroll
                for (int nt = 0; nt < 8; nt++)
                    mma16(acc[mt][nt], af[c][mt], bfr[c][nt]);
        }
        __syncthreads();
        buf ^= 1;
    }

    // epilogue: c0:(g,2t) c1:(g,2t+1) c2:(g+8,2t) c3:(g+8,2t+1)
    #pragma unroll
    for (int mt = 0; mt < 4; mt++) {
        const int r0 = bm + wm * 64 + mt * 16 + g;
        float bm0 = 0.f, bm1 = 0.f;
        if (!BIASN && bias) { bm0 = bias[r0]; bm1 = bias[r0 + 8]; }
        #pragma unroll
        for (int nt = 0; nt < 8; nt++) {
            const int c0 = bn + wn * 64 + nt * 8 + 2 * t;
            float v00 = acc[mt][nt][0] * alpha + bm0;
            float v01 = acc[mt][nt][1] * alpha + bm0;
            float v10 = acc[mt][nt][2] * alpha + bm1;
            float v11 = acc[mt][nt][3] * alpha + bm1;
            if (BIASN && bias) {
                const float bn0 = bias[c0], bn1 = bias[c0 + 1];
                v00 += bn0; v01 += bn1; v10 += bn0; v11 += bn1;
            }
            if (R) {
                const float2 r0v = *(const float2*)&R[(long long)r0 * ldc + c0];
                const float2 r1v = *(const float2*)&R[(long long)(r0 + 8) * ldc + c0];
                v00 += r0v.x; v01 += r0v.y;
                v10 += r1v.x; v11 += r1v.y;
            }
            store_pair(C, (long long)r0 * ldc + c0, v00, v01);
            store_pair(C, (long long)(r0 + 8) * ldc + c0, v10, v11);
        }
    }
}

// ---------------- row softmax: fp32 S -> bf16 P --------------------------------
__global__ void __launch_bounds__(256)
softmax_kernel(const float* __restrict__ sm, __nv_bfloat16* __restrict__ pm)
{
    const float* row = sm + (long long)blockIdx.x * LL;
    __nv_bfloat16* prow = pm + (long long)blockIdx.x * LL;
    const int tid = threadIdx.x;
    const int warp = tid >> 5, lane = tid & 31;

    float v[8];
    float mx = -1e30f;
    #pragma unroll
    for (int i = 0; i < 8; i++) {
        v[i] = row[tid + 256 * i];
        mx = fmaxf(mx, v[i]);
    }
    __shared__ float red[32];
    __shared__ float bcast;
    #pragma unroll
    for (int o = 16; o; o >>= 1) mx = fmaxf(mx, __shfl_xor_sync(0xffffffffu, mx, o));
    if (!lane) red[warp] = mx;
    __syncthreads();
    if (tid < 32) {
        float m2 = (tid < 8) ? red[tid] : -1e30f;
        #pragma unroll
        for (int o = 4; o; o >>= 1) m2 = fmaxf(m2, __shfl_xor_sync(0xffffffffu, m2, o));
        if (!tid) bcast = m2;
    }
    __syncthreads();
    mx = bcast;

    float s = 0.f;
    #pragma unroll
    for (int i = 0; i < 8; i++) {
        v[i] = expf(v[i] - mx);
        s += v[i];
    }
    #pragma unroll
    for (int o = 16; o; o >>= 1) s += __shfl_xor_sync(0xffffffffu, s, o);
    if (!lane) red[warp] = s;
    __syncthreads();
    if (tid < 32) {
        float s2 = (tid < 8) ? red[tid] : 0.f;
        #pragma unroll
        for (int o = 4; o; o >>= 1) s2 += __shfl_xor_sync(0xffffffffu, s2, o);
        if (!tid) bcast = s2;
    }
    __syncthreads();
    const float inv = 1.f / bcast;
    #pragma unroll
    for (int i = 0; i < 8; i++)
        prow[tid + 256 * i] = __float2bfloat16_rn(v[i] * inv);
}

// ---------------- launch ------------------------------------------------------
extern "C" void kernel_launch(void* const* d_in, const int* in_sizes, int n_in,
                              void* d_out, int out_size)
{
    const float* x  = (const float*)d_in[0];
    const float* gw = (const float*)d_in[1];
    const float* gb = (const float*)d_in[2];
    const float* wq = (const float*)d_in[3];
    const float* bq = (const float*)d_in[4];
    const float* wk = (const float*)d_in[5];
    const float* bk = (const float*)d_in[6];
    const float* wv = (const float*)d_in[7];
    const float* bv = (const float*)d_in[8];
    const float* wo = (const float*)d_in[9];
    const float* bo = (const float*)d_in[10];
    float* out = (float*)d_out;

    __nv_bfloat16 *ht, *qk, *v, *h2, *p, *wh;
    float *s, *bc;
    cudaGetSymbolAddress((void**)&ht, g_ht);
    cudaGetSymbolAddress((void**)&qk, g_qk);
    cudaGetSymbolAddress((void**)&v,  g_v);
    cudaGetSymbolAddress((void**)&h2, g_h2);
    cudaGetSymbolAddress((void**)&s,  g_s);
    cudaGetSymbolAddress((void**)&p,  g_p);
    cudaGetSymbolAddress((void**)&wh, g_wh);
    cudaGetSymbolAddress((void**)&bc, g_bc);

    __nv_bfloat16* wqk = wh;                    // [2C][C]: wq rows then wk rows
    __nv_bfloat16* wvh = wh + 2 * CC * CC;      // [C][C]
    __nv_bfloat16* woh = wh + 3 * CC * CC;      // [C][C]

    const float scale = 0.044194173824159216f;   // 512^-0.5
    dim3 blk(128);

    // 0) bf16 weights + bias concat
    cvtb_kernel<<<1024, 256>>>((const float4*)wq, (const float4*)wk,
                               (const float4*)wv, (const float4*)wo,
                               (__nv_bfloat162*)wh);
    bcat_kernel<<<4, 256>>>(bq, bk, bc);

    // 1) GroupNorm -> hT [L][C] bf16
    gn_kernel<<<BB * NG, 256>>>(x, gw, gb, ht);

    // 2) qkT[L][2C] = hT @ wqk^T + (bq|bk)   (M=L, N=2C, K=C)
    gemm_bf16<true, __nv_bfloat16><<<dim3(2 * CC / BN, LL / BM, BB), blk>>>(
        ht, CL, CC, wqk, 0LL, CC, bc, nullptr, 0LL,
        qk, 2 * CL, 2 * CC, CC, 1.f);

    // 3) v[C][L] = wv @ h + bv   (M=C, N=L, K=C; B = hT [L][C])
    gemm_bf16<false, __nv_bfloat16><<<dim3(LL / BN, CC / BM, BB), blk>>>(
        wvh, 0LL, CC, ht, CL, CC, bv, nullptr, 0LL,
        v, CL, LL, CC, 1.f);

    // 4) S = scale * q @ k^T   (M=L, N=L, K=C; A = qkT[:, :C], B = qkT[:, C:])
    gemm_bf16<false, float><<<dim3(LL / BN, LL / BM, BB), blk>>>(
        qk, 2 * CL, 2 * CC, qk + CC, 2 * CL, 2 * CC, nullptr, nullptr, 0LL,
        s, LL2, LL, CC, scale);

    // 5) row softmax: S fp32 -> P bf16
    softmax_kernel<<<BB * LL, 256>>>(s, p);

    // 6) h2T[L][C] = P @ v^T   (M=L, N=C, K=L; B = v [C][L])
    gemm_bf16<false, __nv_bfloat16><<<dim3(CC / BN, LL / BM, BB), blk>>>(
        p, LL2, LL, v, CL, LL, nullptr, nullptr, 0LL,
        h2, CL, CC, LL, 1.f);

    // 7) out = x + wo @ h2 + bo   (M=C, N=L, K=C; B = h2T [L][C])
    gemm_bf16<false, float><<<dim3(LL / BN, CC / BM, BB), blk>>>(
        woh, 0LL, CC, h2, CL, CC, bo, x, CL,
        out, CL, LL, CC, 1.f);
}